// round 1
// baseline (speedup 1.0000x reference)
#include <cuda_runtime.h>
#include <cstddef>
#include <cstdint>

#define NV 100000
#define NF 200000
#define DD 512

// ---------------- scratch (static device arrays; no allocation) ----------------
__device__ float g_Y[(size_t)NV * DD];      // features @ W1  (per-vertex)
__device__ float g_h1[(size_t)NF * DD];     // relu(mean-gather(Y) + b1)
__device__ float g_h2[(size_t)NF * DD];     // relu(h1 @ W2 + b2)
__device__ float g_h3[(size_t)NF * 256];    // relu(h2 @ W3 + b3)
__device__ float g_out12[(size_t)NF * 12];  // h3 @ W4 + b4
__device__ float g_sum[(size_t)NV * 3];
__device__ float g_cnt[NV];

// ---------------- tiled fp32 GEMM: C = [relu](A @ B [+ bias]) ----------------
// A: [M,K] row-major, B: [K,N] row-major. 128x128 tile, BK=8, 256 threads, 8x8/thread.
template<bool RELU, bool BIAS>
__global__ void __launch_bounds__(256, 2)
sgemm(const float* __restrict__ A, const float* __restrict__ B,
      const float* __restrict__ bias, float* __restrict__ C,
      int M, int N, int K)
{
    __shared__ float As[2][8][128];
    __shared__ float Bs[2][8][128];
    const int tid  = threadIdx.x;
    const int bm   = blockIdx.y * 128;
    const int bn   = blockIdx.x * 128;
    const int arow = tid >> 1;
    const int acol = (tid & 1) << 2;
    const int brow = tid >> 5;
    const int bcol = (tid & 31) << 2;
    const int tx   = tid & 15;
    const int ty   = tid >> 4;

    const int grow = bm + arow;
    const float* Aptr = A + (size_t)grow * K + acol;
    const float* Bptr = B + (size_t)brow * N + bn + bcol;

    float acc[8][8];
    #pragma unroll
    for (int i = 0; i < 8; i++)
        #pragma unroll
        for (int j = 0; j < 8; j++) acc[i][j] = 0.0f;

    const int nk = K >> 3;

    // prologue: load k-tile 0 into buffer 0
    {
        float4 av = make_float4(0.f, 0.f, 0.f, 0.f);
        if (grow < M) av = *reinterpret_cast<const float4*>(Aptr);
        float4 bv = *reinterpret_cast<const float4*>(Bptr);
        As[0][acol + 0][arow] = av.x;
        As[0][acol + 1][arow] = av.y;
        As[0][acol + 2][arow] = av.z;
        As[0][acol + 3][arow] = av.w;
        *reinterpret_cast<float4*>(&Bs[0][brow][bcol]) = bv;
    }
    __syncthreads();

    for (int kt = 0; kt < nk; kt++) {
        const int cb = kt & 1;
        if (kt + 1 < nk) {
            const int nb = cb ^ 1;
            float4 av = make_float4(0.f, 0.f, 0.f, 0.f);
            if (grow < M) av = *reinterpret_cast<const float4*>(Aptr + (size_t)(kt + 1) * 8);
            float4 bv = *reinterpret_cast<const float4*>(Bptr + (size_t)(kt + 1) * 8 * N);
            As[nb][acol + 0][arow] = av.x;
            As[nb][acol + 1][arow] = av.y;
            As[nb][acol + 2][arow] = av.z;
            As[nb][acol + 3][arow] = av.w;
            *reinterpret_cast<float4*>(&Bs[nb][brow][bcol]) = bv;
        }
        #pragma unroll
        for (int kk = 0; kk < 8; kk++) {
            float a[8], b[8];
            #pragma unroll
            for (int i = 0; i < 8; i++) a[i] = As[cb][kk][ty * 8 + i];
            #pragma unroll
            for (int j = 0; j < 8; j++) b[j] = Bs[cb][kk][tx * 8 + j];
            #pragma unroll
            for (int i = 0; i < 8; i++)
                #pragma unroll
                for (int j = 0; j < 8; j++)
                    acc[i][j] = fmaf(a[i], b[j], acc[i][j]);
        }
        __syncthreads();
    }

    float bias_r[8];
    #pragma unroll
    for (int j = 0; j < 8; j++) bias_r[j] = BIAS ? bias[bn + tx * 8 + j] : 0.0f;

    #pragma unroll
    for (int i = 0; i < 8; i++) {
        const int row = bm + ty * 8 + i;
        if (row < M) {
            float v[8];
            #pragma unroll
            for (int j = 0; j < 8; j++) {
                float x = acc[i][j] + bias_r[j];
                if (RELU) x = fmaxf(x, 0.0f);
                v[j] = x;
            }
            float* cp = C + (size_t)row * N + bn + tx * 8;
            *reinterpret_cast<float4*>(cp + 0) = make_float4(v[0], v[1], v[2], v[3]);
            *reinterpret_cast<float4*>(cp + 4) = make_float4(v[4], v[5], v[6], v[7]);
        }
    }
}

// -------------- gather-mean + bias + relu: h1[f] = relu((Y[i0]+Y[i1]+Y[i2])/3 + b1) --------------
__global__ void gather_mean_relu(const int* __restrict__ faces, const float* __restrict__ b1)
{
    const int f = blockIdx.x;
    const int c = threadIdx.x;           // 128 threads -> 128 float4 = 512 floats
    const int i0 = faces[3 * f + 0];
    const int i1 = faces[3 * f + 1];
    const int i2 = faces[3 * f + 2];
    const float4 a = reinterpret_cast<const float4*>(g_Y + (size_t)i0 * DD)[c];
    const float4 b = reinterpret_cast<const float4*>(g_Y + (size_t)i1 * DD)[c];
    const float4 d = reinterpret_cast<const float4*>(g_Y + (size_t)i2 * DD)[c];
    const float4 bb = reinterpret_cast<const float4*>(b1)[c];
    const float s = 1.0f / 3.0f;
    float4 o;
    o.x = fmaxf((a.x + b.x + d.x) * s + bb.x, 0.0f);
    o.y = fmaxf((a.y + b.y + d.y) * s + bb.y, 0.0f);
    o.z = fmaxf((a.z + b.z + d.z) * s + bb.z, 0.0f);
    o.w = fmaxf((a.w + b.w + d.w) * s + bb.w, 0.0f);
    reinterpret_cast<float4*>(g_h1 + (size_t)f * DD)[c] = o;
}

// -------------- small final GEMM: out12 = h3 @ W4 + b4  (N=12, K=256) --------------
__global__ void __launch_bounds__(256)
final_gemm(const float* __restrict__ W4, const float* __restrict__ b4)
{
    __shared__ float sW[256 * 12];
    __shared__ float sb[12];
    for (int i = threadIdx.x; i < 256 * 12; i += 256) sW[i] = W4[i];
    if (threadIdx.x < 12) sb[threadIdx.x] = b4[threadIdx.x];
    __syncthreads();

    const int f = blockIdx.x * 256 + threadIdx.x;
    if (f >= NF) return;
    float acc[12];
    #pragma unroll
    for (int j = 0; j < 12; j++) acc[j] = sb[j];

    const float4* row = reinterpret_cast<const float4*>(g_h3 + (size_t)f * 256);
    #pragma unroll 4
    for (int k4 = 0; k4 < 64; k4++) {
        const float4 v = row[k4];
        const int k = k4 * 4;
        #pragma unroll
        for (int j = 0; j < 12; j++) acc[j] = fmaf(v.x, sW[(k + 0) * 12 + j], acc[j]);
        #pragma unroll
        for (int j = 0; j < 12; j++) acc[j] = fmaf(v.y, sW[(k + 1) * 12 + j], acc[j]);
        #pragma unroll
        for (int j = 0; j < 12; j++) acc[j] = fmaf(v.z, sW[(k + 2) * 12 + j], acc[j]);
        #pragma unroll
        for (int j = 0; j < 12; j++) acc[j] = fmaf(v.w, sW[(k + 3) * 12 + j], acc[j]);
    }
    float* op = g_out12 + (size_t)f * 12;
    #pragma unroll
    for (int j = 0; j < 12; j++) op[j] = acc[j];
}

// -------------- zero the scatter accumulators --------------
__global__ void zero_buffers()
{
    const int i = blockIdx.x * blockDim.x + threadIdx.x;
    if (i < NV * 3) g_sum[i] = 0.0f;
    if (i < NV) g_cnt[i] = 0.0f;
}

// -------------- procrustes (Horn quaternion / 4x4 Jacobi) + transform + scatter --------------
__global__ void __launch_bounds__(256)
procrustes_scatter(const float* __restrict__ verts, const int* __restrict__ faces,
                   float* __restrict__ out)
{
    const int f = blockIdx.x * blockDim.x + threadIdx.x;
    if (f >= NF) return;

    const float* o = g_out12 + (size_t)f * 12;
    const float m0 = o[0], m1 = o[1], m2 = o[2];
    const float m3 = o[3], m4 = o[4], m5 = o[5];
    const float m6 = o[6], m7 = o[7], m8 = o[8];
    const float t0 = o[9], t1 = o[10], t2 = o[11];

    // Horn's 4x4 K matrix: q^T K q = tr(R(q)^T M), maximize over unit q.
    float A[4][4];
    A[0][0] =  m0 + m4 + m8;
    A[1][1] =  m0 - m4 - m8;
    A[2][2] = -m0 + m4 - m8;
    A[3][3] = -m0 - m4 + m8;
    A[0][1] = A[1][0] = m7 - m5;
    A[0][2] = A[2][0] = m2 - m6;
    A[0][3] = A[3][0] = m3 - m1;
    A[1][2] = A[2][1] = m1 + m3;
    A[1][3] = A[3][1] = m2 + m6;
    A[2][3] = A[3][2] = m5 + m7;

    float V[4][4] = {{1,0,0,0},{0,1,0,0},{0,0,1,0},{0,0,0,1}};

    #pragma unroll 1
    for (int sweep = 0; sweep < 8; sweep++) {
        #pragma unroll
        for (int pi = 0; pi < 6; pi++) {
            const int p = (pi < 3) ? 0 : ((pi < 5) ? 1 : 2);
            const int q = (pi == 0) ? 1 : ((pi == 1 || pi == 3) ? 2 : 3);
            const float apq = A[p][q];
            if (fabsf(apq) < 1e-30f) continue;
            const float tau = (A[q][q] - A[p][p]) / (2.0f * apq);
            const float tt  = copysignf(1.0f, tau) / (fabsf(tau) + sqrtf(tau * tau + 1.0f));
            const float c   = rsqrtf(tt * tt + 1.0f);
            const float s   = tt * c;
            A[p][p] = A[p][p] - tt * apq;
            A[q][q] = A[q][q] + tt * apq;
            A[p][q] = A[q][p] = 0.0f;
            #pragma unroll
            for (int r = 0; r < 4; r++) {
                if (r == p || r == q) continue;
                const float arp = A[r][p], arq = A[r][q];
                A[r][p] = A[p][r] = c * arp - s * arq;
                A[r][q] = A[q][r] = s * arp + c * arq;
            }
            #pragma unroll
            for (int r = 0; r < 4; r++) {
                const float vrp = V[r][p], vrq = V[r][q];
                V[r][p] = c * vrp - s * vrq;
                V[r][q] = s * vrp + c * vrq;
            }
        }
    }

    // pick eigenvector of max eigenvalue (compile-time column indices)
    float qw = V[0][0], qx = V[1][0], qy = V[2][0], qz = V[3][0];
    float bd = A[0][0];
    if (A[1][1] > bd) { bd = A[1][1]; qw = V[0][1]; qx = V[1][1]; qy = V[2][1]; qz = V[3][1]; }
    if (A[2][2] > bd) { bd = A[2][2]; qw = V[0][2]; qx = V[1][2]; qy = V[2][2]; qz = V[3][2]; }
    if (A[3][3] > bd) { bd = A[3][3]; qw = V[0][3]; qx = V[1][3]; qy = V[2][3]; qz = V[3][3]; }
    const float qn = rsqrtf(qw * qw + qx * qx + qy * qy + qz * qz);
    qw *= qn; qx *= qn; qy *= qn; qz *= qn;

    float R[3][3];
    R[0][0] = 1.0f - 2.0f * (qy * qy + qz * qz);
    R[0][1] = 2.0f * (qx * qy - qw * qz);
    R[0][2] = 2.0f * (qx * qz + qw * qy);
    R[1][0] = 2.0f * (qx * qy + qw * qz);
    R[1][1] = 1.0f - 2.0f * (qx * qx + qz * qz);
    R[1][2] = 2.0f * (qy * qz - qw * qx);
    R[2][0] = 2.0f * (qx * qz - qw * qy);
    R[2][1] = 2.0f * (qy * qz + qw * qx);
    R[2][2] = 1.0f - 2.0f * (qx * qx + qy * qy);

    // rotations output
    float* ro = out + (size_t)(NV * 3) + (size_t)NF * 9 + (size_t)f * 9;
    #pragma unroll
    for (int i = 0; i < 3; i++)
        #pragma unroll
        for (int j = 0; j < 3; j++) ro[i * 3 + j] = R[i][j];

    // transformed prism + scatter
    float* tp = out + (size_t)(NV * 3) + (size_t)f * 9;
    #pragma unroll
    for (int i = 0; i < 3; i++) {
        const int vi = faces[3 * f + i];
        const float px = verts[3 * vi + 0];
        const float py = verts[3 * vi + 1];
        const float pz = verts[3 * vi + 2];
        const float ox = px * R[0][0] + py * R[1][0] + pz * R[2][0] + t0;
        const float oy = px * R[0][1] + py * R[1][1] + pz * R[2][1] + t1;
        const float oz = px * R[0][2] + py * R[1][2] + pz * R[2][2] + t2;
        tp[i * 3 + 0] = ox;
        tp[i * 3 + 1] = oy;
        tp[i * 3 + 2] = oz;
        atomicAdd(&g_sum[(size_t)vi * 3 + 0], ox);
        atomicAdd(&g_sum[(size_t)vi * 3 + 1], oy);
        atomicAdd(&g_sum[(size_t)vi * 3 + 2], oz);
        atomicAdd(&g_cnt[vi], 1.0f);
    }
}

// -------------- segment mean finalize --------------
__global__ void finalize(float* __restrict__ out)
{
    const int v = blockIdx.x * blockDim.x + threadIdx.x;
    if (v >= NV) return;
    const float c = fmaxf(g_cnt[v], 1.0f);
    out[v * 3 + 0] = g_sum[v * 3 + 0] / c;
    out[v * 3 + 1] = g_sum[v * 3 + 1] / c;
    out[v * 3 + 2] = g_sum[v * 3 + 2] / c;
}

// ---------------- host launcher ----------------
extern "C" void kernel_launch(void* const* d_in, const int* in_sizes, int n_in,
                              void* d_out, int out_size)
{
    const float* verts    = (const float*)d_in[0];
    const float* features = (const float*)d_in[1];
    const int*   faces    = (const int*)d_in[2];
    const float* W1 = (const float*)d_in[3];
    const float* b1 = (const float*)d_in[4];
    const float* W2 = (const float*)d_in[5];
    const float* b2 = (const float*)d_in[6];
    const float* W3 = (const float*)d_in[7];
    const float* b3 = (const float*)d_in[8];
    const float* W4 = (const float*)d_in[9];
    const float* b4 = (const float*)d_in[10];
    float* out = (float*)d_out;

    void *pY, *ph1, *ph2, *ph3;
    cudaGetSymbolAddress(&pY,  g_Y);
    cudaGetSymbolAddress(&ph1, g_h1);
    cudaGetSymbolAddress(&ph2, g_h2);
    cudaGetSymbolAddress(&ph3, g_h3);

    // zero scatter accumulators (graph replays must start fresh)
    zero_buffers<<<(NV * 3 + 255) / 256, 256>>>();

    // Y = features @ W1   (M=NV, N=512, K=512)
    {
        dim3 grid(512 / 128, (NV + 127) / 128);
        sgemm<false, false><<<grid, 256>>>(features, W1, nullptr, (float*)pY, NV, 512, 512);
    }
    // h1 = relu(mean-gather(Y) + b1)
    gather_mean_relu<<<NF, 128>>>(faces, b1);
    // h2 = relu(h1 @ W2 + b2)   (M=NF, N=512, K=512)
    {
        dim3 grid(512 / 128, (NF + 127) / 128);
        sgemm<true, true><<<grid, 256>>>((const float*)ph1, W2, b2, (float*)ph2, NF, 512, 512);
    }
    // h3 = relu(h2 @ W3 + b3)   (M=NF, N=256, K=512)
    {
        dim3 grid(256 / 128, (NF + 127) / 128);
        sgemm<true, true><<<grid, 256>>>((const float*)ph2, W3, b3, (float*)ph3, NF, 256, 512);
    }
    // out12 = h3 @ W4 + b4
    final_gemm<<<(NF + 255) / 256, 256>>>(W4, b4);
    // procrustes + transform + scatter
    procrustes_scatter<<<(NF + 255) / 256, 256>>>(verts, faces, out);
    // segment mean
    finalize<<<(NV + 255) / 256, 256>>>(out);
}

// round 4
// speedup vs baseline: 1.3588x; 1.3588x over previous
#include <cuda_runtime.h>
#include <cuda_bf16.h>
#include <cstddef>
#include <cstdint>

#define NV 100000
#define NF 200000
#define DD 512

// ---------------- scratch (static device arrays; no allocation) ----------------
__device__ __align__(256) __nv_bfloat16 g_fhi[(size_t)NV * DD];
__device__ __align__(256) __nv_bfloat16 g_flo[(size_t)NV * DD];
__device__ __align__(256) float         g_Y[(size_t)NV * DD];
__device__ __align__(256) __nv_bfloat16 g_h1hi[(size_t)NF * DD];
__device__ __align__(256) __nv_bfloat16 g_h1lo[(size_t)NF * DD];
__device__ __align__(256) __nv_bfloat16 g_h2hi[(size_t)NF * DD];
__device__ __align__(256) __nv_bfloat16 g_h2lo[(size_t)NF * DD];
__device__ __align__(256) float         g_h3[(size_t)NF * 256];
__device__ __align__(256) __nv_bfloat16 g_B1hi[DD * DD];
__device__ __align__(256) __nv_bfloat16 g_B1lo[DD * DD];
__device__ __align__(256) __nv_bfloat16 g_B2hi[DD * DD];
__device__ __align__(256) __nv_bfloat16 g_B2lo[DD * DD];
__device__ __align__(256) __nv_bfloat16 g_B3hi[256 * DD];
__device__ __align__(256) __nv_bfloat16 g_B3lo[256 * DD];
__device__ __align__(256) float         g_out12[(size_t)NF * 12];
__device__ __align__(256) float         g_sum[(size_t)NV * 3];
__device__ __align__(256) float         g_cnt[NV];

// ---------------- HMMA GEMM helpers ----------------
#define CP16(dst, src) \
    asm volatile("cp.async.cg.shared.global.L2::128B [%0], [%1], 16;" :: "r"(dst), "l"(src) : "memory")

__device__ __forceinline__ void ldm_x4(uint32_t& r0, uint32_t& r1, uint32_t& r2, uint32_t& r3,
                                       uint32_t addr) {
    asm volatile("ldmatrix.sync.aligned.m8n8.x4.shared.b16 {%0,%1,%2,%3}, [%4];"
                 : "=r"(r0), "=r"(r1), "=r"(r2), "=r"(r3) : "r"(addr));
}

__device__ __forceinline__ void mma_bf16(float* c, const uint32_t* a, uint32_t b0, uint32_t b1) {
    asm volatile("mma.sync.aligned.m16n8k16.row.col.f32.bf16.bf16.f32 "
                 "{%0,%1,%2,%3}, {%4,%5,%6,%7}, {%8,%9}, {%0,%1,%2,%3};"
                 : "+f"(c[0]), "+f"(c[1]), "+f"(c[2]), "+f"(c[3])
                 : "r"(a[0]), "r"(a[1]), "r"(a[2]), "r"(a[3]), "r"(b0), "r"(b1));
}

// ---------------- HMMA GEMM: C = [relu]( (Ahi+Alo) @ (Bhi+Blo)^T [+bias] ) ----------------
// A: [M,K] row-major bf16 hi/lo.  B: [N,K] row-major bf16 hi/lo (W transposed).
// Block tile 128x128, 256 threads = 8 warps (4 along M x 2 along N), warp tile 32x64.
// K-chunk 32, double-buffered cp.async. Rows padded: 40 bf16 (80 B) stride.
// Stage layout: Ah@0, Al@10240, Bh@20480, Bl@30720. Stage stride 40960. Total smem 81920.
#define ROWB 80u
#define MATB 10240u
#define STAGEB 40960u
#define GEMM_SMEM_BYTES (2 * STAGEB)

template<bool RELU, bool BIAS, bool OUTF32>
__global__ void __launch_bounds__(256, 1)
gemm_mma(const __nv_bfloat16* __restrict__ Ahi, const __nv_bfloat16* __restrict__ Alo,
         const __nv_bfloat16* __restrict__ Bhi, const __nv_bfloat16* __restrict__ Blo,
         const float* __restrict__ bias,
         float* __restrict__ Cf, __nv_bfloat16* __restrict__ Chi, __nv_bfloat16* __restrict__ Clo,
         int M, int N, int K)
{
    extern __shared__ __align__(256) char smem[];
    const uint32_t sbase = (uint32_t)__cvta_generic_to_shared(smem);
    const int tid = threadIdx.x;
    const int wid = tid >> 5;
    const int lid = tid & 31;
    const int wm = (wid & 3) * 32;       // warp M offset in tile
    const int wn = (wid >> 2) * 64;      // warp N offset in tile
    const int bm = blockIdx.y * 128;
    const int bn = blockIdx.x * 128;
    const int NK = K >> 5;               // K-chunks of 32

    // ldmatrix lane-address components
    const int a_row = ((lid >> 3) & 1) * 8 + (lid & 7);
    const int a_k   = (lid >> 4) * 8;
    const int b_row = (lid >> 4) * 8 + (lid & 7);
    const int b_k   = ((lid >> 3) & 1) * 8;

    float acc[2][8][4];
    #pragma unroll
    for (int i = 0; i < 2; i++)
        #pragma unroll
        for (int j = 0; j < 8; j++)
            #pragma unroll
            for (int q = 0; q < 4; q++) acc[i][j][q] = 0.0f;

    auto load_stage = [&](int kt) {
        const uint32_t sb = sbase + (uint32_t)(kt & 1) * STAGEB;
        const int kc = kt << 5;
        #pragma unroll
        for (int i = 0; i < 2; i++) {
            const int c = tid + i * 256;           // 0..511
            const int r = c >> 2, k16 = c & 3;
            int gr = bm + r; if (gr >= M) gr = M - 1;
            const size_t aoff = (size_t)gr * K + kc + k16 * 8;
            const uint32_t da = sb + r * ROWB + k16 * 16;
            CP16(da,        Ahi + aoff);
            CP16(da + MATB, Alo + aoff);
            const size_t boff = (size_t)(bn + r) * K + kc + k16 * 8;
            const uint32_t db = sb + 2 * MATB + r * ROWB + k16 * 16;
            CP16(db,        Bhi + boff);
            CP16(db + MATB, Blo + boff);
        }
        asm volatile("cp.async.commit_group;" ::: "memory");
    };

    load_stage(0);

    for (int kt = 0; kt < NK; kt++) {
        if (kt + 1 < NK) {
            load_stage(kt + 1);
            asm volatile("cp.async.wait_group 1;" ::: "memory");
        } else {
            asm volatile("cp.async.wait_group 0;" ::: "memory");
        }
        __syncthreads();

        const uint32_t sb = sbase + (uint32_t)(kt & 1) * STAGEB;
        #pragma unroll
        for (int ks = 0; ks < 32; ks += 16) {
            uint32_t ah[2][4], al[2][4], bh[4][4], bl[4][4];
            #pragma unroll
            for (int mi = 0; mi < 2; mi++) {
                const uint32_t ra = sb + (uint32_t)(wm + mi * 16 + a_row) * ROWB
                                  + (uint32_t)(ks + a_k) * 2;
                ldm_x4(ah[mi][0], ah[mi][1], ah[mi][2], ah[mi][3], ra);
                ldm_x4(al[mi][0], al[mi][1], al[mi][2], al[mi][3], ra + MATB);
            }
            #pragma unroll
            for (int nt = 0; nt < 4; nt++) {
                const uint32_t rb = sb + 2 * MATB + (uint32_t)(wn + nt * 16 + b_row) * ROWB
                                  + (uint32_t)(ks + b_k) * 2;
                ldm_x4(bh[nt][0], bh[nt][1], bh[nt][2], bh[nt][3], rb);
                ldm_x4(bl[nt][0], bl[nt][1], bl[nt][2], bl[nt][3], rb + MATB);
            }
            #pragma unroll
            for (int mi = 0; mi < 2; mi++) {
                #pragma unroll
                for (int nt = 0; nt < 4; nt++) {
                    mma_bf16(acc[mi][2 * nt],     ah[mi], bh[nt][0], bh[nt][1]);
                    mma_bf16(acc[mi][2 * nt + 1], ah[mi], bh[nt][2], bh[nt][3]);
                    mma_bf16(acc[mi][2 * nt],     ah[mi], bl[nt][0], bl[nt][1]);
                    mma_bf16(acc[mi][2 * nt + 1], ah[mi], bl[nt][2], bl[nt][3]);
                    mma_bf16(acc[mi][2 * nt],     al[mi], bh[nt][0], bh[nt][1]);
                    mma_bf16(acc[mi][2 * nt + 1], al[mi], bh[nt][2], bh[nt][3]);
                }
            }
        }
        __syncthreads();
    }

    // ---------------- epilogue ----------------
    // acc[mi][ni][0..1]: row = bm+wm+mi*16+lid/4,     cols = cn, cn+1
    // acc[mi][ni][2..3]: row = +8
    #pragma unroll
    for (int mi = 0; mi < 2; mi++) {
        #pragma unroll
        for (int half = 0; half < 2; half++) {
            const int row = bm + wm + mi * 16 + (lid >> 2) + half * 8;
            if (row >= M) continue;
            #pragma unroll
            for (int ni = 0; ni < 8; ni++) {
                const int cn = bn + wn + ni * 8 + 2 * (lid & 3);
                float x0 = acc[mi][ni][2 * half + 0];
                float x1 = acc[mi][ni][2 * half + 1];
                if (BIAS) { x0 += bias[cn]; x1 += bias[cn + 1]; }
                if (RELU) { x0 = fmaxf(x0, 0.0f); x1 = fmaxf(x1, 0.0f); }
                const size_t off = (size_t)row * N + cn;
                if (OUTF32) {
                    *reinterpret_cast<float2*>(Cf + off) = make_float2(x0, x1);
                } else {
                    const __nv_bfloat16 h0 = __float2bfloat16(x0);
                    const __nv_bfloat16 h1 = __float2bfloat16(x1);
                    const __nv_bfloat16 l0 = __float2bfloat16(x0 - __bfloat162float(h0));
                    const __nv_bfloat16 l1 = __float2bfloat16(x1 - __bfloat162float(h1));
                    __nv_bfloat162 th(h0, h1), tl(l0, l1);
                    *reinterpret_cast<uint32_t*>(Chi + off) = *reinterpret_cast<uint32_t*>(&th);
                    *reinterpret_cast<uint32_t*>(Clo + off) = *reinterpret_cast<uint32_t*>(&tl);
                }
            }
        }
    }
}

// ---------------- conversions ----------------
__global__ void conv_split(const float* __restrict__ X, __nv_bfloat16* __restrict__ hi,
                           __nv_bfloat16* __restrict__ lo, size_t n)
{
    const size_t i = (size_t)blockIdx.x * blockDim.x + threadIdx.x;
    if (i >= n) return;
    const float x = X[i];
    const __nv_bfloat16 h = __float2bfloat16(x);
    hi[i] = h;
    lo[i] = __float2bfloat16(x - __bfloat162float(h));
}

// W: [K,N] row-major fp32 -> B: [N,K] row-major bf16 hi/lo
__global__ void convT_split(const float* __restrict__ W, __nv_bfloat16* __restrict__ hi,
                            __nv_bfloat16* __restrict__ lo, int K, int N)
{
    const int idx = blockIdx.x * blockDim.x + threadIdx.x;
    if (idx >= K * N) return;
    const int n = idx / K;
    const int k = idx - n * K;
    const float x = W[(size_t)k * N + n];
    const __nv_bfloat16 h = __float2bfloat16(x);
    hi[idx] = h;
    lo[idx] = __float2bfloat16(x - __bfloat162float(h));
}

// -------------- gather-mean + bias + relu -> h1 hi/lo --------------
__global__ void gather_mean_relu(const int* __restrict__ faces, const float* __restrict__ b1)
{
    const int f = blockIdx.x;
    const int c = threadIdx.x;           // 128 threads -> 128 float4 = 512 floats
    const int i0 = faces[3 * f + 0];
    const int i1 = faces[3 * f + 1];
    const int i2 = faces[3 * f + 2];
    const float4 a = reinterpret_cast<const float4*>(g_Y + (size_t)i0 * DD)[c];
    const float4 b = reinterpret_cast<const float4*>(g_Y + (size_t)i1 * DD)[c];
    const float4 d = reinterpret_cast<const float4*>(g_Y + (size_t)i2 * DD)[c];
    const float4 bb = reinterpret_cast<const float4*>(b1)[c];
    const float s = 1.0f / 3.0f;
    float o[4];
    o[0] = fmaxf((a.x + b.x + d.x) * s + bb.x, 0.0f);
    o[1] = fmaxf((a.y + b.y + d.y) * s + bb.y, 0.0f);
    o[2] = fmaxf((a.z + b.z + d.z) * s + bb.z, 0.0f);
    o[3] = fmaxf((a.w + b.w + d.w) * s + bb.w, 0.0f);

    uint32_t hp[2], lp[2];
    #pragma unroll
    for (int jj = 0; jj < 2; jj++) {
        const __nv_bfloat16 ha = __float2bfloat16(o[2 * jj]);
        const __nv_bfloat16 hb = __float2bfloat16(o[2 * jj + 1]);
        const __nv_bfloat16 la = __float2bfloat16(o[2 * jj] - __bfloat162float(ha));
        const __nv_bfloat16 lb = __float2bfloat16(o[2 * jj + 1] - __bfloat162float(hb));
        __nv_bfloat162 th(ha, hb), tl(la, lb);
        hp[jj] = *reinterpret_cast<uint32_t*>(&th);
        lp[jj] = *reinterpret_cast<uint32_t*>(&tl);
    }
    const size_t off = (size_t)f * DD + c * 4;
    *reinterpret_cast<uint2*>(g_h1hi + off) = make_uint2(hp[0], hp[1]);
    *reinterpret_cast<uint2*>(g_h1lo + off) = make_uint2(lp[0], lp[1]);
}

// -------------- small final GEMM: out12 = h3 @ W4 + b4  (N=12, K=256) --------------
__global__ void __launch_bounds__(256)
final_gemm(const float* __restrict__ W4, const float* __restrict__ b4)
{
    __shared__ float sW[256 * 12];
    __shared__ float sb[12];
    for (int i = threadIdx.x; i < 256 * 12; i += 256) sW[i] = W4[i];
    if (threadIdx.x < 12) sb[threadIdx.x] = b4[threadIdx.x];
    __syncthreads();

    const int f = blockIdx.x * 256 + threadIdx.x;
    if (f >= NF) return;
    float acc[12];
    #pragma unroll
    for (int j = 0; j < 12; j++) acc[j] = sb[j];

    const float4* row = reinterpret_cast<const float4*>(g_h3 + (size_t)f * 256);
    #pragma unroll 4
    for (int k4 = 0; k4 < 64; k4++) {
        const float4 v = row[k4];
        const int k = k4 * 4;
        #pragma unroll
        for (int j = 0; j < 12; j++) acc[j] = fmaf(v.x, sW[(k + 0) * 12 + j], acc[j]);
        #pragma unroll
        for (int j = 0; j < 12; j++) acc[j] = fmaf(v.y, sW[(k + 1) * 12 + j], acc[j]);
        #pragma unroll
        for (int j = 0; j < 12; j++) acc[j] = fmaf(v.z, sW[(k + 2) * 12 + j], acc[j]);
        #pragma unroll
        for (int j = 0; j < 12; j++) acc[j] = fmaf(v.w, sW[(k + 3) * 12 + j], acc[j]);
    }
    float* op = g_out12 + (size_t)f * 12;
    #pragma unroll
    for (int j = 0; j < 12; j++) op[j] = acc[j];
}

// -------------- zero the scatter accumulators --------------
__global__ void zero_buffers()
{
    const int i = blockIdx.x * blockDim.x + threadIdx.x;
    if (i < NV * 3) g_sum[i] = 0.0f;
    if (i < NV) g_cnt[i] = 0.0f;
}

// -------------- procrustes (Horn quaternion / 4x4 Jacobi) + transform + scatter --------------
__global__ void __launch_bounds__(256)
procrustes_scatter(const float* __restrict__ verts, const int* __restrict__ faces,
                   float* __restrict__ out)
{
    const int f = blockIdx.x * blockDim.x + threadIdx.x;
    if (f >= NF) return;

    const float* o = g_out12 + (size_t)f * 12;
    const float m0 = o[0], m1 = o[1], m2 = o[2];
    const float m3 = o[3], m4 = o[4], m5 = o[5];
    const float m6 = o[6], m7 = o[7], m8 = o[8];
    const float t0 = o[9], t1 = o[10], t2 = o[11];

    float A[4][4];
    A[0][0] =  m0 + m4 + m8;
    A[1][1] =  m0 - m4 - m8;
    A[2][2] = -m0 + m4 - m8;
    A[3][3] = -m0 - m4 + m8;
    A[0][1] = A[1][0] = m7 - m5;
    A[0][2] = A[2][0] = m2 - m6;
    A[0][3] = A[3][0] = m3 - m1;
    A[1][2] = A[2][1] = m1 + m3;
    A[1][3] = A[3][1] = m2 + m6;
    A[2][3] = A[3][2] = m5 + m7;

    float V[4][4] = {{1,0,0,0},{0,1,0,0},{0,0,1,0},{0,0,0,1}};

    #pragma unroll 1
    for (int sweep = 0; sweep < 8; sweep++) {
        #pragma unroll
        for (int pi = 0; pi < 6; pi++) {
            const int p = (pi < 3) ? 0 : ((pi < 5) ? 1 : 2);
            const int q = (pi == 0) ? 1 : ((pi == 1 || pi == 3) ? 2 : 3);
            const float apq = A[p][q];
            if (fabsf(apq) < 1e-30f) continue;
            const float tau = (A[q][q] - A[p][p]) / (2.0f * apq);
            const float tt  = copysignf(1.0f, tau) / (fabsf(tau) + sqrtf(tau * tau + 1.0f));
            const float c   = rsqrtf(tt * tt + 1.0f);
            const float s   = tt * c;
            A[p][p] = A[p][p] - tt * apq;
            A[q][q] = A[q][q] + tt * apq;
            A[p][q] = A[q][p] = 0.0f;
            #pragma unroll
            for (int r = 0; r < 4; r++) {
                if (r == p || r == q) continue;
                const float arp = A[r][p], arq = A[r][q];
                A[r][p] = A[p][r] = c * arp - s * arq;
                A[r][q] = A[q][r] = s * arp + c * arq;
            }
            #pragma unroll
            for (int r = 0; r < 4; r++) {
                const float vrp = V[r][p], vrq = V[r][q];
                V[r][p] = c * vrp - s * vrq;
                V[r][q] = s * vrp + c * vrq;
            }
        }
    }

    float qw = V[0][0], qx = V[1][0], qy = V[2][0], qz = V[3][0];
    float bd = A[0][0];
    if (A[1][1] > bd) { bd = A[1][1]; qw = V[0][1]; qx = V[1][1]; qy = V[2][1]; qz = V[3][1]; }
    if (A[2][2] > bd) { bd = A[2][2]; qw = V[0][2]; qx = V[1][2]; qy = V[2][2]; qz = V[3][2]; }
    if (A[3][3] > bd) { bd = A[3][3]; qw = V[0][3]; qx = V[1][3]; qy = V[2][3]; qz = V[3][3]; }
    const float qn = rsqrtf(qw * qw + qx * qx + qy * qy + qz * qz);
    qw *= qn; qx *= qn; qy *= qn; qz *= qn;

    float R[3][3];
    R[0][0] = 1.0f - 2.0f * (qy * qy + qz * qz);
    R[0][1] = 2.0f * (qx * qy - qw * qz);
    R[0][2] = 2.0f * (qx * qz + qw * qy);
    R[1][0] = 2.0f * (qx * qy + qw * qz);
    R[1][1] = 1.0f - 2.0f * (qx * qx + qz * qz);
    R[1][2] = 2.0f * (qy * qz - qw * qx);
    R[2][0] = 2.0f * (qx * qz - qw * qy);
    R[2][1] = 2.0f * (qy * qz + qw * qx);
    R[2][2] = 1.0f - 2.0f * (qx * qx + qy * qy);

    float* ro = out + (size_t)(NV * 3) + (size_t)NF * 9 + (size_t)f * 9;
    #pragma unroll
    for (int i = 0; i < 3; i++)
        #pragma unroll
        for (int j = 0; j < 3; j++) ro[i * 3 + j] = R[i][j];

    float* tp = out + (size_t)(NV * 3) + (size_t)f * 9;
    #pragma unroll
    for (int i = 0; i < 3; i++) {
        const int vi = faces[3 * f + i];
        const float px = verts[3 * vi + 0];
        const float py = verts[3 * vi + 1];
        const float pz = verts[3 * vi + 2];
        const float ox = px * R[0][0] + py * R[1][0] + pz * R[2][0] + t0;
        const float oy = px * R[0][1] + py * R[1][1] + pz * R[2][1] + t1;
        const float oz = px * R[0][2] + py * R[1][2] + pz * R[2][2] + t2;
        tp[i * 3 + 0] = ox;
        tp[i * 3 + 1] = oy;
        tp[i * 3 + 2] = oz;
        atomicAdd(&g_sum[(size_t)vi * 3 + 0], ox);
        atomicAdd(&g_sum[(size_t)vi * 3 + 1], oy);
        atomicAdd(&g_sum[(size_t)vi * 3 + 2], oz);
        atomicAdd(&g_cnt[vi], 1.0f);
    }
}

// -------------- segment mean finalize --------------
__global__ void finalize(float* __restrict__ out)
{
    const int v = blockIdx.x * blockDim.x + threadIdx.x;
    if (v >= NV) return;
    const float c = fmaxf(g_cnt[v], 1.0f);
    out[v * 3 + 0] = g_sum[v * 3 + 0] / c;
    out[v * 3 + 1] = g_sum[v * 3 + 1] / c;
    out[v * 3 + 2] = g_sum[v * 3 + 2] / c;
}

// ---------------- host launcher ----------------
extern "C" void kernel_launch(void* const* d_in, const int* in_sizes, int n_in,
                              void* d_out, int out_size)
{
    const float* verts    = (const float*)d_in[0];
    const float* features = (const float*)d_in[1];
    const int*   faces    = (const int*)d_in[2];
    const float* W1 = (const float*)d_in[3];
    const float* b1 = (const float*)d_in[4];
    const float* W2 = (const float*)d_in[5];
    const float* b2 = (const float*)d_in[6];
    const float* W3 = (const float*)d_in[7];
    const float* b3 = (const float*)d_in[8];
    const float* W4 = (const float*)d_in[9];
    const float* b4 = (const float*)d_in[10];
    float* out = (float*)d_out;

    void *pfhi, *pflo, *pY, *ph1hi, *ph1lo, *ph2hi, *ph2lo, *ph3;
    void *pB1hi, *pB1lo, *pB2hi, *pB2lo, *pB3hi, *pB3lo;
    cudaGetSymbolAddress(&pfhi,  g_fhi);
    cudaGetSymbolAddress(&pflo,  g_flo);
    cudaGetSymbolAddress(&pY,    g_Y);
    cudaGetSymbolAddress(&ph1hi, g_h1hi);
    cudaGetSymbolAddress(&ph1lo, g_h1lo);
    cudaGetSymbolAddress(&ph2hi, g_h2hi);
    cudaGetSymbolAddress(&ph2lo, g_h2lo);
    cudaGetSymbolAddress(&ph3,   g_h3);
    cudaGetSymbolAddress(&pB1hi, g_B1hi);
    cudaGetSymbolAddress(&pB1lo, g_B1lo);
    cudaGetSymbolAddress(&pB2hi, g_B2hi);
    cudaGetSymbolAddress(&pB2lo, g_B2lo);
    cudaGetSymbolAddress(&pB3hi, g_B3hi);
    cudaGetSymbolAddress(&pB3lo, g_B3lo);

    cudaFuncSetAttribute(gemm_mma<false, false, true>,
                         cudaFuncAttributeMaxDynamicSharedMemorySize, GEMM_SMEM_BYTES);
    cudaFuncSetAttribute(gemm_mma<true, true, false>,
                         cudaFuncAttributeMaxDynamicSharedMemorySize, GEMM_SMEM_BYTES);
    cudaFuncSetAttribute(gemm_mma<true, true, true>,
                         cudaFuncAttributeMaxDynamicSharedMemorySize, GEMM_SMEM_BYTES);

    zero_buffers<<<(NV * 3 + 255) / 256, 256>>>();

    // conversions
    {
        const size_t nf = (size_t)NV * DD;
        conv_split<<<(unsigned)((nf + 255) / 256), 256>>>(features, (__nv_bfloat16*)pfhi,
                                                          (__nv_bfloat16*)pflo, nf);
        convT_split<<<(DD * DD + 255) / 256, 256>>>(W1, (__nv_bfloat16*)pB1hi, (__nv_bfloat16*)pB1lo, DD, DD);
        convT_split<<<(DD * DD + 255) / 256, 256>>>(W2, (__nv_bfloat16*)pB2hi, (__nv_bfloat16*)pB2lo, DD, DD);
        convT_split<<<(DD * 256 + 255) / 256, 256>>>(W3, (__nv_bfloat16*)pB3hi, (__nv_bfloat16*)pB3lo, DD, 256);
    }

    // Y = features @ W1   (M=NV, N=512, K=512) — fp32 out, no bias/relu
    gemm_mma<false, false, true><<<dim3(4, (NV + 127) / 128), 256, GEMM_SMEM_BYTES>>>(
        (const __nv_bfloat16*)pfhi, (const __nv_bfloat16*)pflo,
        (const __nv_bfloat16*)pB1hi, (const __nv_bfloat16*)pB1lo,
        nullptr, (float*)pY, nullptr, nullptr, NV, 512, 512);

    // h1 = relu(mean-gather(Y) + b1)  -> hi/lo
    gather_mean_relu<<<NF, 128>>>(faces, b1);

    // h2 = relu(h1 @ W2 + b2)  -> hi/lo
    gemm_mma<true, true, false><<<dim3(4, (NF + 127) / 128), 256, GEMM_SMEM_BYTES>>>(
        (const __nv_bfloat16*)ph1hi, (const __nv_bfloat16*)ph1lo,
        (const __nv_bfloat16*)pB2hi, (const __nv_bfloat16*)pB2lo,
        b2, nullptr, (__nv_bfloat16*)ph2hi, (__nv_bfloat16*)ph2lo, NF, 512, 512);

    // h3 = relu(h2 @ W3 + b3)  -> fp32
    gemm_mma<true, true, true><<<dim3(2, (NF + 127) / 128), 256, GEMM_SMEM_BYTES>>>(
        (const __nv_bfloat16*)ph2hi, (const __nv_bfloat16*)ph2lo,
        (const __nv_bfloat16*)pB3hi, (const __nv_bfloat16*)pB3lo,
        b3, (float*)ph3, nullptr, nullptr, NF, 256, 512);

    // out12 = h3 @ W4 + b4
    final_gemm<<<(NF + 255) / 256, 256>>>(W4, b4);
    // procrustes + transform + scatter
    procrustes_scatter<<<(NF + 255) / 256, 256>>>(verts, faces, out);
    // segment mean
    finalize<<<(NV + 255) / 256, 256>>>(out);
}

// round 5
// speedup vs baseline: 2.1090x; 1.5520x over previous
#include <cuda_runtime.h>
#include <cuda_bf16.h>
#include <cstddef>
#include <cstdint>

#define NV 100000
#define NF 200000
#define DD 512

// ---------------- scratch (static device arrays; no allocation) ----------------
__device__ __align__(256) __nv_bfloat16 g_fhi[(size_t)NV * DD];
__device__ __align__(256) __nv_bfloat16 g_flo[(size_t)NV * DD];
__device__ __align__(256) float         g_Y[(size_t)NV * DD];
__device__ __align__(256) __nv_bfloat16 g_h1hi[(size_t)NF * DD];
__device__ __align__(256) __nv_bfloat16 g_h1lo[(size_t)NF * DD];
__device__ __align__(256) __nv_bfloat16 g_h2hi[(size_t)NF * DD];
__device__ __align__(256) __nv_bfloat16 g_h2lo[(size_t)NF * DD];
__device__ __align__(256) float         g_h3[(size_t)NF * 256];
__device__ __align__(256) __nv_bfloat16 g_B1hi[DD * DD];
__device__ __align__(256) __nv_bfloat16 g_B1lo[DD * DD];
__device__ __align__(256) __nv_bfloat16 g_B2hi[DD * DD];
__device__ __align__(256) __nv_bfloat16 g_B2lo[DD * DD];
__device__ __align__(256) __nv_bfloat16 g_B3hi[256 * DD];
__device__ __align__(256) __nv_bfloat16 g_B3lo[256 * DD];
__device__ __align__(256) float         g_out12[(size_t)NF * 12];
__device__ __align__(256) float         g_sum[(size_t)NV * 3];
__device__ __align__(256) float         g_cnt[NV];

// ---------------- HMMA GEMM helpers ----------------
#define CP16(dst, src) \
    asm volatile("cp.async.cg.shared.global.L2::128B [%0], [%1], 16;" :: "r"(dst), "l"(src) : "memory")

__device__ __forceinline__ void ldm_x4(uint32_t& r0, uint32_t& r1, uint32_t& r2, uint32_t& r3,
                                       uint32_t addr) {
    asm volatile("ldmatrix.sync.aligned.m8n8.x4.shared.b16 {%0,%1,%2,%3}, [%4];"
                 : "=r"(r0), "=r"(r1), "=r"(r2), "=r"(r3) : "r"(addr));
}

__device__ __forceinline__ void mma_bf16(float* c, const uint32_t* a, uint32_t b0, uint32_t b1) {
    asm volatile("mma.sync.aligned.m16n8k16.row.col.f32.bf16.bf16.f32 "
                 "{%0,%1,%2,%3}, {%4,%5,%6,%7}, {%8,%9}, {%0,%1,%2,%3};"
                 : "+f"(c[0]), "+f"(c[1]), "+f"(c[2]), "+f"(c[3])
                 : "r"(a[0]), "r"(a[1]), "r"(a[2]), "r"(a[3]), "r"(b0), "r"(b1));
}

// ---------------- HMMA GEMM: C = [relu]( (Ahi+Alo) @ (Bhi+Blo)^T [+bias] ) ----------------
// A: [M,K] row-major bf16 hi/lo.  B: [N,K] row-major bf16 hi/lo (W transposed).
// Block tile 128x128, 256 threads = 8 warps (4 along M x 2 along N), warp tile 32x64.
// K-chunk 32, 3-stage cp.async ring, one __syncthreads per K-iter.
// Rows padded to 80 B. Stage: Ah@0, Al@10240, Bh@20480, Bl@30720; stride 40960.
#define ROWB 80u
#define MATB 10240u
#define STAGEB 40960u
#define GEMM_SMEM_BYTES (3 * STAGEB)

template<bool RELU, bool BIAS, bool OUTF32>
__global__ void __launch_bounds__(256, 1)
gemm_mma(const __nv_bfloat16* __restrict__ Ahi, const __nv_bfloat16* __restrict__ Alo,
         const __nv_bfloat16* __restrict__ Bhi, const __nv_bfloat16* __restrict__ Blo,
         const float* __restrict__ bias,
         float* __restrict__ Cf, __nv_bfloat16* __restrict__ Chi, __nv_bfloat16* __restrict__ Clo,
         int M, int N, int K)
{
    extern __shared__ __align__(256) char smem[];
    const uint32_t sbase = (uint32_t)__cvta_generic_to_shared(smem);
    const int tid = threadIdx.x;
    const int wid = tid >> 5;
    const int lid = tid & 31;
    const int wm = (wid & 3) * 32;       // warp M offset in tile
    const int wn = (wid >> 2) * 64;      // warp N offset in tile
    const int bm = blockIdx.y * 128;
    const int bn = blockIdx.x * 128;
    const int NK = K >> 5;               // K-chunks of 32

    // ldmatrix lane-address components
    const int a_row = ((lid >> 3) & 1) * 8 + (lid & 7);
    const int a_k   = (lid >> 4) * 8;
    const int b_row = (lid >> 4) * 8 + (lid & 7);
    const int b_k   = ((lid >> 3) & 1) * 8;

    float acc[2][8][4];
    #pragma unroll
    for (int i = 0; i < 2; i++)
        #pragma unroll
        for (int j = 0; j < 8; j++)
            #pragma unroll
            for (int q = 0; q < 4; q++) acc[i][j][q] = 0.0f;

    auto load_stage = [&](int kt, int buf) {
        const uint32_t sb = sbase + (uint32_t)buf * STAGEB;
        const int kc = kt << 5;
        #pragma unroll
        for (int i = 0; i < 2; i++) {
            const int c = tid + i * 256;           // 0..511
            const int r = c >> 2, k16 = c & 3;
            int gr = bm + r; if (gr >= M) gr = M - 1;
            const size_t aoff = (size_t)gr * K + kc + k16 * 8;
            const uint32_t da = sb + r * ROWB + k16 * 16;
            CP16(da,        Ahi + aoff);
            CP16(da + MATB, Alo + aoff);
            const size_t boff = (size_t)(bn + r) * K + kc + k16 * 8;
            const uint32_t db = sb + 2 * MATB + r * ROWB + k16 * 16;
            CP16(db,        Bhi + boff);
            CP16(db + MATB, Blo + boff);
        }
        asm volatile("cp.async.commit_group;" ::: "memory");
    };

    // A-fragment loader (double-buffered across ks), B loaded just-in-time.
    uint32_t ah[2][2][4], al[2][2][4];

    auto load_a_frags = [&](uint32_t sb, int slot, int ks) {
        #pragma unroll
        for (int mi = 0; mi < 2; mi++) {
            const uint32_t ra = sb + (uint32_t)(wm + mi * 16 + a_row) * ROWB
                              + (uint32_t)(ks + a_k) * 2;
            ldm_x4(ah[slot][mi][0], ah[slot][mi][1], ah[slot][mi][2], ah[slot][mi][3], ra);
            ldm_x4(al[slot][mi][0], al[slot][mi][1], al[slot][mi][2], al[slot][mi][3], ra + MATB);
        }
    };

    // prologue: stages 0 and 1 in flight
    load_stage(0, 0);
    if (NK > 1) load_stage(1, 1);

    int cb = 0;          // compute buffer
    int pb = 2;          // prefetch buffer (for kt+2)

    for (int kt = 0; kt < NK; kt++) {
        asm volatile("cp.async.wait_group 1;" ::: "memory");
        __syncthreads();
        if (kt + 2 < NK) load_stage(kt + 2, pb);

        const uint32_t sb = sbase + (uint32_t)cb * STAGEB;
        load_a_frags(sb, 0, 0);

        #pragma unroll
        for (int ksi = 0; ksi < 2; ksi++) {
            const int ks = ksi * 16;
            if (ksi == 0) load_a_frags(sb, 1, 16);   // prefetch next A frags

            uint32_t bh[4][4], bl[4][4];
            #pragma unroll
            for (int nt = 0; nt < 4; nt++) {
                const uint32_t rb = sb + 2 * MATB + (uint32_t)(wn + nt * 16 + b_row) * ROWB
                                  + (uint32_t)(ks + b_k) * 2;
                ldm_x4(bh[nt][0], bh[nt][1], bh[nt][2], bh[nt][3], rb);
                ldm_x4(bl[nt][0], bl[nt][1], bl[nt][2], bl[nt][3], rb + MATB);
            }
            #pragma unroll
            for (int mi = 0; mi < 2; mi++) {
                #pragma unroll
                for (int nt = 0; nt < 4; nt++) {
                    mma_bf16(acc[mi][2 * nt],     ah[ksi][mi], bh[nt][0], bh[nt][1]);
                    mma_bf16(acc[mi][2 * nt + 1], ah[ksi][mi], bh[nt][2], bh[nt][3]);
                    mma_bf16(acc[mi][2 * nt],     ah[ksi][mi], bl[nt][0], bl[nt][1]);
                    mma_bf16(acc[mi][2 * nt + 1], ah[ksi][mi], bl[nt][2], bl[nt][3]);
                    mma_bf16(acc[mi][2 * nt],     al[ksi][mi], bh[nt][0], bh[nt][1]);
                    mma_bf16(acc[mi][2 * nt + 1], al[ksi][mi], bh[nt][2], bh[nt][3]);
                }
            }
        }
        // no trailing sync: buffer cb is only overwritten by load_stage(kt+3),
        // which is issued after the NEXT iteration's __syncthreads.
        cb = (cb + 1 == 3) ? 0 : cb + 1;
        pb = (pb + 1 == 3) ? 0 : pb + 1;
    }

    // ---------------- epilogue ----------------
    // acc[mi][ni][0..1]: row = bm+wm+mi*16+lid/4, cols = cn, cn+1 ; [2..3]: row+8
    #pragma unroll
    for (int mi = 0; mi < 2; mi++) {
        #pragma unroll
        for (int half = 0; half < 2; half++) {
            const int row = bm + wm + mi * 16 + (lid >> 2) + half * 8;
            if (row >= M) continue;
            #pragma unroll
            for (int ni = 0; ni < 8; ni++) {
                const int cn = bn + wn + ni * 8 + 2 * (lid & 3);
                float x0 = acc[mi][ni][2 * half + 0];
                float x1 = acc[mi][ni][2 * half + 1];
                if (BIAS) { x0 += bias[cn]; x1 += bias[cn + 1]; }
                if (RELU) { x0 = fmaxf(x0, 0.0f); x1 = fmaxf(x1, 0.0f); }
                const size_t off = (size_t)row * N + cn;
                if (OUTF32) {
                    *reinterpret_cast<float2*>(Cf + off) = make_float2(x0, x1);
                } else {
                    const __nv_bfloat16 h0 = __float2bfloat16(x0);
                    const __nv_bfloat16 h1 = __float2bfloat16(x1);
                    const __nv_bfloat16 l0 = __float2bfloat16(x0 - __bfloat162float(h0));
                    const __nv_bfloat16 l1 = __float2bfloat16(x1 - __bfloat162float(h1));
                    __nv_bfloat162 th(h0, h1), tl(l0, l1);
                    *reinterpret_cast<uint32_t*>(Chi + off) = *reinterpret_cast<uint32_t*>(&th);
                    *reinterpret_cast<uint32_t*>(Clo + off) = *reinterpret_cast<uint32_t*>(&tl);
                }
            }
        }
    }
}

// ---------------- conversions ----------------
__global__ void conv_split(const float* __restrict__ X, __nv_bfloat16* __restrict__ hi,
                           __nv_bfloat16* __restrict__ lo, size_t n)
{
    const size_t i = (size_t)blockIdx.x * blockDim.x + threadIdx.x;
    if (i >= n) return;
    const float x = X[i];
    const __nv_bfloat16 h = __float2bfloat16(x);
    hi[i] = h;
    lo[i] = __float2bfloat16(x - __bfloat162float(h));
}

// W: [K,N] row-major fp32 -> B: [N,K] row-major bf16 hi/lo
__global__ void convT_split(const float* __restrict__ W, __nv_bfloat16* __restrict__ hi,
                            __nv_bfloat16* __restrict__ lo, int K, int N)
{
    const int idx = blockIdx.x * blockDim.x + threadIdx.x;
    if (idx >= K * N) return;
    const int n = idx / K;
    const int k = idx - n * K;
    const float x = W[(size_t)k * N + n];
    const __nv_bfloat16 h = __float2bfloat16(x);
    hi[idx] = h;
    lo[idx] = __float2bfloat16(x - __bfloat162float(h));
}

// -------------- gather-mean + bias + relu -> h1 hi/lo --------------
__global__ void gather_mean_relu(const int* __restrict__ faces, const float* __restrict__ b1)
{
    const int f = blockIdx.x;
    const int c = threadIdx.x;           // 128 threads -> 128 float4 = 512 floats
    const int i0 = faces[3 * f + 0];
    const int i1 = faces[3 * f + 1];
    const int i2 = faces[3 * f + 2];
    const float4 a = reinterpret_cast<const float4*>(g_Y + (size_t)i0 * DD)[c];
    const float4 b = reinterpret_cast<const float4*>(g_Y + (size_t)i1 * DD)[c];
    const float4 d = reinterpret_cast<const float4*>(g_Y + (size_t)i2 * DD)[c];
    const float4 bb = reinterpret_cast<const float4*>(b1)[c];
    const float s = 1.0f / 3.0f;
    float o[4];
    o[0] = fmaxf((a.x + b.x + d.x) * s + bb.x, 0.0f);
    o[1] = fmaxf((a.y + b.y + d.y) * s + bb.y, 0.0f);
    o[2] = fmaxf((a.z + b.z + d.z) * s + bb.z, 0.0f);
    o[3] = fmaxf((a.w + b.w + d.w) * s + bb.w, 0.0f);

    uint32_t hp[2], lp[2];
    #pragma unroll
    for (int jj = 0; jj < 2; jj++) {
        const __nv_bfloat16 ha = __float2bfloat16(o[2 * jj]);
        const __nv_bfloat16 hb = __float2bfloat16(o[2 * jj + 1]);
        const __nv_bfloat16 la = __float2bfloat16(o[2 * jj] - __bfloat162float(ha));
        const __nv_bfloat16 lb = __float2bfloat16(o[2 * jj + 1] - __bfloat162float(hb));
        __nv_bfloat162 th(ha, hb), tl(la, lb);
        hp[jj] = *reinterpret_cast<uint32_t*>(&th);
        lp[jj] = *reinterpret_cast<uint32_t*>(&tl);
    }
    const size_t off = (size_t)f * DD + c * 4;
    *reinterpret_cast<uint2*>(g_h1hi + off) = make_uint2(hp[0], hp[1]);
    *reinterpret_cast<uint2*>(g_h1lo + off) = make_uint2(lp[0], lp[1]);
}

// -------------- small final GEMM: out12 = h3 @ W4 + b4  (N=12, K=256) --------------
__global__ void __launch_bounds__(256)
final_gemm(const float* __restrict__ W4, const float* __restrict__ b4)
{
    __shared__ float sW[256 * 12];
    __shared__ float sb[12];
    for (int i = threadIdx.x; i < 256 * 12; i += 256) sW[i] = W4[i];
    if (threadIdx.x < 12) sb[threadIdx.x] = b4[threadIdx.x];
    __syncthreads();

    const int f = blockIdx.x * 256 + threadIdx.x;
    if (f >= NF) return;
    float acc[12];
    #pragma unroll
    for (int j = 0; j < 12; j++) acc[j] = sb[j];

    const float4* row = reinterpret_cast<const float4*>(g_h3 + (size_t)f * 256);
    #pragma unroll 4
    for (int k4 = 0; k4 < 64; k4++) {
        const float4 v = row[k4];
        const int k = k4 * 4;
        #pragma unroll
        for (int j = 0; j < 12; j++) acc[j] = fmaf(v.x, sW[(k + 0) * 12 + j], acc[j]);
        #pragma unroll
        for (int j = 0; j < 12; j++) acc[j] = fmaf(v.y, sW[(k + 1) * 12 + j], acc[j]);
        #pragma unroll
        for (int j = 0; j < 12; j++) acc[j] = fmaf(v.z, sW[(k + 2) * 12 + j], acc[j]);
        #pragma unroll
        for (int j = 0; j < 12; j++) acc[j] = fmaf(v.w, sW[(k + 3) * 12 + j], acc[j]);
    }
    float* op = g_out12 + (size_t)f * 12;
    #pragma unroll
    for (int j = 0; j < 12; j++) op[j] = acc[j];
}

// -------------- zero the scatter accumulators --------------
__global__ void zero_buffers()
{
    const int i = blockIdx.x * blockDim.x + threadIdx.x;
    if (i < NV * 3) g_sum[i] = 0.0f;
    if (i < NV) g_cnt[i] = 0.0f;
}

// -------------- procrustes (Horn quaternion / 4x4 Jacobi) + transform + scatter --------------
__global__ void __launch_bounds__(256)
procrustes_scatter(const float* __restrict__ verts, const int* __restrict__ faces,
                   float* __restrict__ out)
{
    const int f = blockIdx.x * blockDim.x + threadIdx.x;
    if (f >= NF) return;

    const float* o = g_out12 + (size_t)f * 12;
    const float m0 = o[0], m1 = o[1], m2 = o[2];
    const float m3 = o[3], m4 = o[4], m5 = o[5];
    const float m6 = o[6], m7 = o[7], m8 = o[8];
    const float t0 = o[9], t1 = o[10], t2 = o[11];

    float A[4][4];
    A[0][0] =  m0 + m4 + m8;
    A[1][1] =  m0 - m4 - m8;
    A[2][2] = -m0 + m4 - m8;
    A[3][3] = -m0 - m4 + m8;
    A[0][1] = A[1][0] = m7 - m5;
    A[0][2] = A[2][0] = m2 - m6;
    A[0][3] = A[3][0] = m3 - m1;
    A[1][2] = A[2][1] = m1 + m3;
    A[1][3] = A[3][1] = m2 + m6;
    A[2][3] = A[3][2] = m5 + m7;

    float V[4][4] = {{1,0,0,0},{0,1,0,0},{0,0,1,0},{0,0,0,1}};

    #pragma unroll 1
    for (int sweep = 0; sweep < 8; sweep++) {
        #pragma unroll
        for (int pi = 0; pi < 6; pi++) {
            const int p = (pi < 3) ? 0 : ((pi < 5) ? 1 : 2);
            const int q = (pi == 0) ? 1 : ((pi == 1 || pi == 3) ? 2 : 3);
            const float apq = A[p][q];
            if (fabsf(apq) < 1e-30f) continue;
            const float tau = (A[q][q] - A[p][p]) / (2.0f * apq);
            const float tt  = copysignf(1.0f, tau) / (fabsf(tau) + sqrtf(tau * tau + 1.0f));
            const float c   = rsqrtf(tt * tt + 1.0f);
            const float s   = tt * c;
            A[p][p] = A[p][p] - tt * apq;
            A[q][q] = A[q][q] + tt * apq;
            A[p][q] = A[q][p] = 0.0f;
            #pragma unroll
            for (int r = 0; r < 4; r++) {
                if (r == p || r == q) continue;
                const float arp = A[r][p], arq = A[r][q];
                A[r][p] = A[p][r] = c * arp - s * arq;
                A[r][q] = A[q][r] = s * arp + c * arq;
            }
            #pragma unroll
            for (int r = 0; r < 4; r++) {
                const float vrp = V[r][p], vrq = V[r][q];
                V[r][p] = c * vrp - s * vrq;
                V[r][q] = s * vrp + c * vrq;
            }
        }
    }

    float qw = V[0][0], qx = V[1][0], qy = V[2][0], qz = V[3][0];
    float bd = A[0][0];
    if (A[1][1] > bd) { bd = A[1][1]; qw = V[0][1]; qx = V[1][1]; qy = V[2][1]; qz = V[3][1]; }
    if (A[2][2] > bd) { bd = A[2][2]; qw = V[0][2]; qx = V[1][2]; qy = V[2][2]; qz = V[3][2]; }
    if (A[3][3] > bd) { bd = A[3][3]; qw = V[0][3]; qx = V[1][3]; qy = V[2][3]; qz = V[3][3]; }
    const float qn = rsqrtf(qw * qw + qx * qx + qy * qy + qz * qz);
    qw *= qn; qx *= qn; qy *= qn; qz *= qn;

    float R[3][3];
    R[0][0] = 1.0f - 2.0f * (qy * qy + qz * qz);
    R[0][1] = 2.0f * (qx * qy - qw * qz);
    R[0][2] = 2.0f * (qx * qz + qw * qy);
    R[1][0] = 2.0f * (qx * qy + qw * qz);
    R[1][1] = 1.0f - 2.0f * (qx * qx + qz * qz);
    R[1][2] = 2.0f * (qy * qz - qw * qx);
    R[2][0] = 2.0f * (qx * qz - qw * qy);
    R[2][1] = 2.0f * (qy * qz + qw * qx);
    R[2][2] = 1.0f - 2.0f * (qx * qx + qy * qy);

    float* ro = out + (size_t)(NV * 3) + (size_t)NF * 9 + (size_t)f * 9;
    #pragma unroll
    for (int i = 0; i < 3; i++)
        #pragma unroll
        for (int j = 0; j < 3; j++) ro[i * 3 + j] = R[i][j];

    float* tp = out + (size_t)(NV * 3) + (size_t)f * 9;
    #pragma unroll
    for (int i = 0; i < 3; i++) {
        const int vi = faces[3 * f + i];
        const float px = verts[3 * vi + 0];
        const float py = verts[3 * vi + 1];
        const float pz = verts[3 * vi + 2];
        const float ox = px * R[0][0] + py * R[1][0] + pz * R[2][0] + t0;
        const float oy = px * R[0][1] + py * R[1][1] + pz * R[2][1] + t1;
        const float oz = px * R[0][2] + py * R[1][2] + pz * R[2][2] + t2;
        tp[i * 3 + 0] = ox;
        tp[i * 3 + 1] = oy;
        tp[i * 3 + 2] = oz;
        atomicAdd(&g_sum[(size_t)vi * 3 + 0], ox);
        atomicAdd(&g_sum[(size_t)vi * 3 + 1], oy);
        atomicAdd(&g_sum[(size_t)vi * 3 + 2], oz);
        atomicAdd(&g_cnt[vi], 1.0f);
    }
}

// -------------- segment mean finalize --------------
__global__ void finalize(float* __restrict__ out)
{
    const int v = blockIdx.x * blockDim.x + threadIdx.x;
    if (v >= NV) return;
    const float c = fmaxf(g_cnt[v], 1.0f);
    out[v * 3 + 0] = g_sum[v * 3 + 0] / c;
    out[v * 3 + 1] = g_sum[v * 3 + 1] / c;
    out[v * 3 + 2] = g_sum[v * 3 + 2] / c;
}

// ---------------- host launcher ----------------
extern "C" void kernel_launch(void* const* d_in, const int* in_sizes, int n_in,
                              void* d_out, int out_size)
{
    const float* verts    = (const float*)d_in[0];
    const float* features = (const float*)d_in[1];
    const int*   faces    = (const int*)d_in[2];
    const float* W1 = (const float*)d_in[3];
    const float* b1 = (const float*)d_in[4];
    const float* W2 = (const float*)d_in[5];
    const float* b2 = (const float*)d_in[6];
    const float* W3 = (const float*)d_in[7];
    const float* b3 = (const float*)d_in[8];
    const float* W4 = (const float*)d_in[9];
    const float* b4 = (const float*)d_in[10];
    float* out = (float*)d_out;

    void *pfhi, *pflo, *pY, *ph1hi, *ph1lo, *ph2hi, *ph2lo, *ph3;
    void *pB1hi, *pB1lo, *pB2hi, *pB2lo, *pB3hi, *pB3lo;
    cudaGetSymbolAddress(&pfhi,  g_fhi);
    cudaGetSymbolAddress(&pflo,  g_flo);
    cudaGetSymbolAddress(&pY,    g_Y);
    cudaGetSymbolAddress(&ph1hi, g_h1hi);
    cudaGetSymbolAddress(&ph1lo, g_h1lo);
    cudaGetSymbolAddress(&ph2hi, g_h2hi);
    cudaGetSymbolAddress(&ph2lo, g_h2lo);
    cudaGetSymbolAddress(&ph3,   g_h3);
    cudaGetSymbolAddress(&pB1hi, g_B1hi);
    cudaGetSymbolAddress(&pB1lo, g_B1lo);
    cudaGetSymbolAddress(&pB2hi, g_B2hi);
    cudaGetSymbolAddress(&pB2lo, g_B2lo);
    cudaGetSymbolAddress(&pB3hi, g_B3hi);
    cudaGetSymbolAddress(&pB3lo, g_B3lo);

    cudaFuncSetAttribute(gemm_mma<false, false, true>,
                         cudaFuncAttributeMaxDynamicSharedMemorySize, GEMM_SMEM_BYTES);
    cudaFuncSetAttribute(gemm_mma<true, true, false>,
                         cudaFuncAttributeMaxDynamicSharedMemorySize, GEMM_SMEM_BYTES);
    cudaFuncSetAttribute(gemm_mma<true, true, true>,
                         cudaFuncAttributeMaxDynamicSharedMemorySize, GEMM_SMEM_BYTES);

    zero_buffers<<<(NV * 3 + 255) / 256, 256>>>();

    // conversions
    {
        const size_t nf = (size_t)NV * DD;
        conv_split<<<(unsigned)((nf + 255) / 256), 256>>>(features, (__nv_bfloat16*)pfhi,
                                                          (__nv_bfloat16*)pflo, nf);
        convT_split<<<(DD * DD + 255) / 256, 256>>>(W1, (__nv_bfloat16*)pB1hi, (__nv_bfloat16*)pB1lo, DD, DD);
        convT_split<<<(DD * DD + 255) / 256, 256>>>(W2, (__nv_bfloat16*)pB2hi, (__nv_bfloat16*)pB2lo, DD, DD);
        convT_split<<<(DD * 256 + 255) / 256, 256>>>(W3, (__nv_bfloat16*)pB3hi, (__nv_bfloat16*)pB3lo, DD, 256);
    }

    // Y = features @ W1   (M=NV, N=512, K=512) — fp32 out, no bias/relu
    gemm_mma<false, false, true><<<dim3(4, (NV + 127) / 128), 256, GEMM_SMEM_BYTES>>>(
        (const __nv_bfloat16*)pfhi, (const __nv_bfloat16*)pflo,
        (const __nv_bfloat16*)pB1hi, (const __nv_bfloat16*)pB1lo,
        nullptr, (float*)pY, nullptr, nullptr, NV, 512, 512);

    // h1 = relu(mean-gather(Y) + b1)  -> hi/lo
    gather_mean_relu<<<NF, 128>>>(faces, b1);

    // h2 = relu(h1 @ W2 + b2)  -> hi/lo
    gemm_mma<true, true, false><<<dim3(4, (NF + 127) / 128), 256, GEMM_SMEM_BYTES>>>(
        (const __nv_bfloat16*)ph1hi, (const __nv_bfloat16*)ph1lo,
        (const __nv_bfloat16*)pB2hi, (const __nv_bfloat16*)pB2lo,
        b2, nullptr, (__nv_bfloat16*)ph2hi, (__nv_bfloat16*)ph2lo, NF, 512, 512);

    // h3 = relu(h2 @ W3 + b3)  -> fp32
    gemm_mma<true, true, true><<<dim3(2, (NF + 127) / 128), 256, GEMM_SMEM_BYTES>>>(
        (const __nv_bfloat16*)ph2hi, (const __nv_bfloat16*)ph2lo,
        (const __nv_bfloat16*)pB3hi, (const __nv_bfloat16*)pB3lo,
        b3, (float*)ph3, nullptr, nullptr, NF, 256, 512);

    // out12 = h3 @ W4 + b4
    final_gemm<<<(NF + 255) / 256, 256>>>(W4, b4);
    // procrustes + transform + scatter
    procrustes_scatter<<<(NF + 255) / 256, 256>>>(verts, faces, out);
    // segment mean
    finalize<<<(NV + 255) / 256, 256>>>(out);
}